// round 1
// baseline (speedup 1.0000x reference)
#include <cuda_runtime.h>

// Dense 3x3 conv, N=32, Cin=Cout=32, H=W=224, stride 1, pad 1, fp32 + bias.
// Strategy: smem-tiled direct conv, register-blocked 8 c_out x 8 pixels per
// thread, packed fp32 FMA (fma.rn.f32x2 -> FFMA2, 2x fp32 throughput).

#define CIN   32
#define COUT  32
#define HH    224
#define WW    224
#define TILE_H 16
#define TILE_W 32
#define SROWS  18            // TILE_H + 2 halo
#define SCOLS  34            // TILE_W + 2 halo
#define SSTRIDE 35           // padded: (3*ty + 8*wg) mod 32 conflict-free
#define X_SMEM (CIN * SROWS * SSTRIDE)   // 20160 floats
#define W_SMEM (COUT * CIN * 9)          // 9216 floats
#define SMEM_FLOATS (X_SMEM + W_SMEM + COUT)

__device__ __forceinline__ unsigned long long pack2(float lo, float hi) {
    unsigned long long r;
    asm("mov.b64 %0, {%1, %2};" : "=l"(r) : "f"(lo), "f"(hi));
    return r;
}
__device__ __forceinline__ void unpack2(unsigned long long v, float& lo, float& hi) {
    asm("mov.b64 {%0, %1}, %2;" : "=f"(lo), "=f"(hi) : "l"(v));
}
__device__ __forceinline__ void fma2(unsigned long long& acc,
                                     unsigned long long a, unsigned long long b) {
    asm("fma.rn.f32x2 %0, %1, %2, %0;" : "+l"(acc) : "l"(a), "l"(b));
}

__global__ __launch_bounds__(256, 1)
void conv3x3_f32x2_kernel(const float* __restrict__ x,
                          const float* __restrict__ wgt,
                          const float* __restrict__ bias,
                          float* __restrict__ out) {
    extern __shared__ float smem[];
    float* sX = smem;                 // [ci][SROWS][SSTRIDE]
    float* sW = smem + X_SMEM;        // [co][ci][9]
    float* sB = sW + W_SMEM;          // [co]

    const int t  = threadIdx.x;
    const int n  = blockIdx.z;
    const int h0 = blockIdx.y * TILE_H;
    const int w0 = blockIdx.x * TILE_W;

    // Stage weights + bias (whole tensor: 36 KB).
    for (int i = t; i < W_SMEM; i += 256) sW[i] = wgt[i];
    if (t < COUT) sB[t] = bias[t];

    // Stage input tile with zero-padded halo.
    const float* xin = x + (size_t)n * CIN * HH * WW;
    for (int idx = t; idx < X_SMEM; idx += 256) {
        int ci  = idx / (SROWS * SSTRIDE);
        int rem = idx - ci * (SROWS * SSTRIDE);
        int r   = rem / SSTRIDE;
        int c   = rem - r * SSTRIDE;
        int gh  = h0 - 1 + r;
        int gw  = w0 - 1 + c;
        float v = 0.0f;
        if (c < SCOLS && (unsigned)gh < HH && (unsigned)gw < WW)
            v = xin[(ci * HH + gh) * WW + gw];
        sX[idx] = v;
    }
    __syncthreads();

    // Thread tiling: co_blk (4 groups of 8 c_out), wg (4 groups of 8 pixels), ty (16 rows).
    const int co_blk = t >> 6;       // 0..3 (constant per warp -> weight LDS broadcast)
    const int rem    = t & 63;
    const int wg     = rem & 3;      // 0..3
    const int ty     = rem >> 2;     // 0..15
    const int wbase  = wg * 8;

    unsigned long long acc[8][4];
#pragma unroll
    for (int co = 0; co < 8; co++) {
        float b = sB[co_blk * 8 + co];
        unsigned long long bb = pack2(b, b);
#pragma unroll
        for (int p = 0; p < 4; p++) acc[co][p] = bb;
    }

#pragma unroll 1
    for (int ci = 0; ci < CIN; ci++) {
        const float* xb = sX + ci * (SROWS * SSTRIDE) + ty * SSTRIDE + wbase;
        float xv[3][10];
#pragma unroll
        for (int dy = 0; dy < 3; dy++)
#pragma unroll
            for (int c = 0; c < 10; c++)
                xv[dy][c] = xb[dy * SSTRIDE + c];

        unsigned long long xp[3][9];
#pragma unroll
        for (int dy = 0; dy < 3; dy++)
#pragma unroll
            for (int c = 0; c < 9; c++)
                xp[dy][c] = pack2(xv[dy][c], xv[dy][c + 1]);

        const float* wp = sW + (co_blk * 8) * (CIN * 9) + ci * 9;
#pragma unroll
        for (int co = 0; co < 8; co++) {
#pragma unroll
            for (int dy = 0; dy < 3; dy++) {
#pragma unroll
                for (int dx = 0; dx < 3; dx++) {
                    float wv = wp[co * (CIN * 9) + dy * 3 + dx];
                    unsigned long long w2 = pack2(wv, wv);
#pragma unroll
                    for (int p = 0; p < 4; p++)
                        fma2(acc[co][p], xp[dy][2 * p + dx], w2);
                }
            }
        }
    }

    // Store: float2 per pixel pair (w-offset even -> 8B aligned).
    float* ob = out + ((size_t)n * COUT + co_blk * 8) * (HH * WW)
                    + (h0 + ty) * WW + (w0 + wbase);
#pragma unroll
    for (int co = 0; co < 8; co++) {
        float2* orow = (float2*)(ob + co * (HH * WW));
#pragma unroll
        for (int p = 0; p < 4; p++) {
            float lo, hi;
            unpack2(acc[co][p], lo, hi);
            orow[p] = make_float2(lo, hi);
        }
    }
}

extern "C" void kernel_launch(void* const* d_in, const int* in_sizes, int n_in,
                              void* d_out, int out_size) {
    const float* x    = (const float*)d_in[0];
    const float* wgt  = (const float*)d_in[1];
    const float* bias = (const float*)d_in[2];
    float* out        = (float*)d_out;

    const int smem_bytes = SMEM_FLOATS * (int)sizeof(float);  // ~117.6 KB
    cudaFuncSetAttribute(conv3x3_f32x2_kernel,
                         cudaFuncAttributeMaxDynamicSharedMemorySize, smem_bytes);

    dim3 grid(WW / TILE_W, HH / TILE_H, 32);   // (7, 14, 32)
    conv3x3_f32x2_kernel<<<grid, 256, smem_bytes>>>(x, wgt, bias, out);
}

// round 3
// speedup vs baseline: 1.3171x; 1.3171x over previous
#include <cuda_runtime.h>

// Dense 3x3 conv, N=32, Cin=Cout=32, H=W=224, stride 1, pad 1, fp32 + bias.
// Round 2 (resubmit; prior attempt hit an infra failure, never ran):
// FFMA2 pairs two adjacent c_out (weights transposed in smem -> broadcast
// LDS.64 weight pairs, no dup movs), 512-thread CTA (4 warps/SMSP).

#define CIN   32
#define COUT  32
#define HH    224
#define WW    224
#define TILE_H 16
#define TILE_W 32
#define SROWS  18            // TILE_H + 2 halo
#define SCOLS  34            // TILE_W + 2 halo
#define SSTRIDE 35           // odd stride: (3*ty + 8*wg + c) mod 32 conflict-free
#define X_SMEM (CIN * SROWS * SSTRIDE)   // 20160 floats (78.75 KB)
#define W_SMEM (CIN * 9 * COUT)          // 9216 floats, transposed [ci][k][co]
#define SMEM_FLOATS (X_SMEM + W_SMEM + COUT)

typedef unsigned long long ull;

__device__ __forceinline__ ull pack2(float lo, float hi) {
    ull r;
    asm("mov.b64 %0, {%1, %2};" : "=l"(r) : "f"(lo), "f"(hi));
    return r;
}
__device__ __forceinline__ void unpack2(ull v, float& lo, float& hi) {
    asm("mov.b64 {%0, %1}, %2;" : "=f"(lo), "=f"(hi) : "l"(v));
}
__device__ __forceinline__ void fma2(ull& acc, ull a, ull b) {
    asm("fma.rn.f32x2 %0, %1, %2, %0;" : "+l"(acc) : "l"(a), "l"(b));
}

__global__ __launch_bounds__(512, 1)
void conv3x3_f32x2_kernel(const float* __restrict__ x,
                          const float* __restrict__ wgt,
                          const float* __restrict__ bias,
                          float* __restrict__ out) {
    extern __shared__ float smem[];
    float* sX = smem;                 // [ci][SROWS][SSTRIDE]
    float* sW = smem + X_SMEM;        // transposed: [ci][k(9)][co(32)]
    float* sB = sW + W_SMEM;          // [co]

    const int t  = threadIdx.x;
    const int n  = blockIdx.z;
    const int h0 = blockIdx.y * TILE_H;
    const int w0 = blockIdx.x * TILE_W;

    // Stage weights TRANSPOSED [ci][k][co] so (co, co+1) pairs are contiguous.
    for (int i = t; i < W_SMEM; i += 512) {
        int ci = i / (9 * COUT);
        int r  = i - ci * (9 * COUT);
        int k  = r >> 5;          // 0..8
        int co = r & 31;
        sW[i] = wgt[(co * CIN + ci) * 9 + k];
    }
    if (t < COUT) sB[t] = bias[t];

    // Stage input tile with zero-padded halo.
    const float* xin = x + (size_t)n * CIN * HH * WW;
    for (int idx = t; idx < X_SMEM; idx += 512) {
        int ci  = idx / (SROWS * SSTRIDE);
        int rem = idx - ci * (SROWS * SSTRIDE);
        int r   = rem / SSTRIDE;
        int c   = rem - r * SSTRIDE;
        int gh  = h0 - 1 + r;
        int gw  = w0 - 1 + c;
        float v = 0.0f;
        if (c < SCOLS && (unsigned)gh < HH && (unsigned)gw < WW)
            v = xin[(ci * HH + gh) * WW + gw];
        sX[idx] = v;
    }
    __syncthreads();

    // Thread tiling: 512 threads = 8 co-blocks (4 c_out each) x 4 wg x 16 ty.
    // co_blk constant per warp -> weight LDS.64 is a uniform broadcast.
    const int co_blk = t >> 6;       // 0..7
    const int rem    = t & 63;
    const int wg     = rem & 3;      // 0..3
    const int ty     = rem >> 2;     // 0..15
    const int wbase  = wg * 8;
    const int co0    = co_blk * 4;

    // acc[cp][p]: lo = out[co0+2cp][p], hi = out[co0+2cp+1][p]
    ull acc[2][8];
#pragma unroll
    for (int cp = 0; cp < 2; cp++) {
        ull bb = pack2(sB[co0 + 2 * cp], sB[co0 + 2 * cp + 1]);
#pragma unroll
        for (int p = 0; p < 8; p++) acc[cp][p] = bb;
    }

#pragma unroll 1
    for (int ci = 0; ci < CIN; ci++) {
        const float* xb = sX + ci * (SROWS * SSTRIDE) + ty * SSTRIDE + wbase;
        const float* wp = sW + ci * (9 * COUT) + co0;

#pragma unroll
        for (int dy = 0; dy < 3; dy++) {
            float xv[10];
#pragma unroll
            for (int c = 0; c < 10; c++) xv[c] = xb[dy * SSTRIDE + c];
            ull xd[10];
#pragma unroll
            for (int c = 0; c < 10; c++) xd[c] = pack2(xv[c], xv[c]);

#pragma unroll
            for (int dx = 0; dx < 3; dx++) {
#pragma unroll
                for (int cp = 0; cp < 2; cp++) {
                    ull w2 = *(const ull*)(wp + (dy * 3 + dx) * COUT + 2 * cp);
#pragma unroll
                    for (int p = 0; p < 8; p++)
                        fma2(acc[cp][p], xd[dx + p], w2);
                }
            }
        }
    }

    // Store: per co row, 8 consecutive pixels -> 2x STG.128 (16B aligned).
    float* ob = out + ((size_t)n * COUT + co0) * (HH * WW)
                    + (h0 + ty) * WW + (w0 + wbase);
#pragma unroll
    for (int cp = 0; cp < 2; cp++) {
        float r0[8], r1[8];
#pragma unroll
        for (int p = 0; p < 8; p++) unpack2(acc[cp][p], r0[p], r1[p]);
        float4* d0 = (float4*)(ob + (size_t)(2 * cp)     * (HH * WW));
        float4* d1 = (float4*)(ob + (size_t)(2 * cp + 1) * (HH * WW));
        d0[0] = make_float4(r0[0], r0[1], r0[2], r0[3]);
        d0[1] = make_float4(r0[4], r0[5], r0[6], r0[7]);
        d1[0] = make_float4(r1[0], r1[1], r1[2], r1[3]);
        d1[1] = make_float4(r1[4], r1[5], r1[6], r1[7]);
    }
}

extern "C" void kernel_launch(void* const* d_in, const int* in_sizes, int n_in,
                              void* d_out, int out_size) {
    const float* x    = (const float*)d_in[0];
    const float* wgt  = (const float*)d_in[1];
    const float* bias = (const float*)d_in[2];
    float* out        = (float*)d_out;

    const int smem_bytes = SMEM_FLOATS * (int)sizeof(float);  // ~115 KB
    cudaFuncSetAttribute(conv3x3_f32x2_kernel,
                         cudaFuncAttributeMaxDynamicSharedMemorySize, smem_bytes);

    dim3 grid(WW / TILE_W, HH / TILE_H, 32);   // (7, 14, 32)
    conv3x3_f32x2_kernel<<<grid, 512, smem_bytes>>>(x, wgt, bias, out);
}